// round 14
// baseline (speedup 1.0000x reference)
#include <cuda_runtime.h>
#include <cuda_fp16.h>
#include <cstdint>

#define NN 8192
#define MM 8192
#define HD 64
#define NH 4
#define LOG2E 1.4426950408889634f

// ---- scratch (device globals; no allocations allowed) ----
__device__ float g_s[NH * NN];                              // pre-scaled by log2e
__device__ float g_d[NH * MM];                              // pre-scaled by log2e
__device__ float g_wfa[NH * 128];
__device__ __align__(16) __half g_E1h[(size_t)NH * MM * HD]; // [h][m][j] 4MB
__device__ uint32_t g_AbT[(size_t)(MM / 32) * NN];          // [m/32][n] 8MB
__device__ float g_np[NH][NN][HD];                          // per-head numerators 8MB
__device__ float g_zp[NH][NN];                              // per-head Z

__device__ __forceinline__ uint32_t smem_u32(const void* p) {
    uint32_t a;
    asm("{ .reg .u64 t; cvta.to.shared.u64 t, %1; cvt.u32.u64 %0, t; }" : "=r"(a) : "l"(p));
    return a;
}
__device__ __forceinline__ uint32_t hadd2u(uint32_t a, uint32_t b) {
    uint32_t r; asm("add.f16x2 %0,%1,%2;" : "=r"(r) : "r"(a), "r"(b)); return r;
}
__device__ __forceinline__ uint32_t hmul2u(uint32_t a, uint32_t b) {
    uint32_t r; asm("mul.f16x2 %0,%1,%2;" : "=r"(r) : "r"(a), "r"(b)); return r;
}
__device__ __forceinline__ uint32_t hmax2u(uint32_t a, uint32_t b) {
    uint32_t r; asm("max.f16x2 %0,%1,%2;" : "=r"(r) : "r"(a), "r"(b)); return r;
}
__device__ __forceinline__ uint32_t ex2h2(uint32_t a) {
    uint32_t r; asm("ex2.approx.f16x2 %0,%1;" : "=r"(r) : "r"(a)); return r;
}
// leaky_relu then exp2 on packed f16x2
__device__ __forceinline__ uint32_t wgen(uint32_t x) {
    return ex2h2(hmax2u(x, hmul2u(x, 0x32663266u)));   // 0x3266 = 0.2f16
}
// mask from 2 bits (bit0 -> low half, bit1 -> high half)
__device__ __forceinline__ uint32_t mk2(uint32_t u) {
    return (u & 1u) * 0xFFFFu + (u & 2u) * 0x7FFF8000u;
}
#define MMA16816(acc, a0, a1, a2, a3, b0, b1)                                  \
    asm volatile("mma.sync.aligned.m16n8k16.row.col.f32.f16.f16.f32 "          \
                 "{%0,%1,%2,%3}, {%4,%5,%6,%7}, {%8,%9}, {%0,%1,%2,%3};"       \
                 : "+f"(acc[0]), "+f"(acc[1]), "+f"(acc[2]), "+f"(acc[3])      \
                 : "r"(a0), "r"(a1), "r"(a2), "r"(a3), "r"(b0), "r"(b1))

// ============================ stage kernels ============================
// wfa: one warp per (h,f) output. 64 blocks x 256 threads = 512 warps.
__global__ void k_wfa(const float* __restrict__ Wf, const float* __restrict__ a) {
    int gw = (blockIdx.x * blockDim.x + threadIdx.x) >> 5;
    int lane = threadIdx.x & 31;
    int h = gw >> 7, f = gw & 127;
    const float* wp = Wf + ((size_t)h * 128 + f) * HD;
    const float* ap = a + h * HD;
    float s = wp[lane] * ap[lane] + wp[lane + 32] * ap[lane + 32];
#pragma unroll
    for (int o = 16; o; o >>= 1) s += __shfl_xor_sync(0xffffffffu, s, o);
    if (lane == 0) g_wfa[gw] = s;
}

// Pack A -> transposed bitmask. 4 independent rows per warp-iteration (MLP=4).
__global__ void k_pack(const int* __restrict__ A) {
    int lane = threadIdx.x & 31;
    int gw = (blockIdx.x * blockDim.x + threadIdx.x) >> 5;
    int nw = (gridDim.x * blockDim.x) >> 5;
    for (int idx = gw; idx < (MM / 32) * (NN / 4); idx += nw) {
        int w = idx & 255;           // MM/32 = 256
        int n4 = idx >> 8;
        const int* base = A + (size_t)(n4 * 4) * MM + w * 32 + lane;
        int v0 = base[0];
        int v1 = base[MM];
        int v2 = base[2 * MM];
        int v3 = base[3 * MM];
        uint32_t b0 = __ballot_sync(0xffffffffu, v0 > 0);
        uint32_t b1 = __ballot_sync(0xffffffffu, v1 > 0);
        uint32_t b2 = __ballot_sync(0xffffffffu, v2 > 0);
        uint32_t b3 = __ballot_sync(0xffffffffu, v3 > 0);
        if (lane == 0) {
            uint32_t* dst = g_AbT + (size_t)w * NN + n4 * 4;
            dst[0] = b0; dst[1] = b1; dst[2] = b2; dst[3] = b3;
        }
    }
}

// s[h,n] = (F0[n,:] . wfa[h,:]) * log2e
__global__ void k_s(const float* __restrict__ F0) {
    int warp = threadIdx.x >> 5, lane = threadIdx.x & 31;
    int gw = blockIdx.x * 8 + warp;
    int n = gw & (NN - 1), h = gw >> 13;
    const float* fp = F0 + (size_t)n * 128;
    const float* wp = g_wfa + h * 128;
    float s = 0.f;
#pragma unroll
    for (int k = 0; k < 4; k++) { int f = lane + k * 32; s += fp[f] * wp[f]; }
#pragma unroll
    for (int o = 16; o; o >>= 1) s += __shfl_xor_sync(0xffffffffu, s, o);
    if (lane == 0) g_s[h * NN + n] = s * LOG2E;
}

// E1h[h][m][j] (f16) and d[h][m]*log2e. 16 m-rows per block (512 blocks):
// each Weh LDG feeds 16 FMAs, plus an 8-deep register prefetch ring, so the
// We L2-latency chain is fully hidden under issue-bound FMA/LDS work.
__global__ __launch_bounds__(256) void k_e1(const float* __restrict__ E0,
                                            const float* __restrict__ We,
                                            const float* __restrict__ a) {
    __shared__ float E0t[128 * 20];      // [e][r], r<16, stride 20 (80B)
    __shared__ float dpart[8][16];
    const int m0 = blockIdx.x * 16;
    const int tid = threadIdx.x;
#pragma unroll
    for (int k = 0; k < 8; k++) {
        int idx = tid + k * 256;         // 2048 elements
        int r = idx >> 7, e = idx & 127;
        E0t[e * 20 + r] = E0[(size_t)(m0 + r) * 128 + e];
    }
    __syncthreads();

    const int h = tid >> 6, j = tid & 63;
    const float* Weh = We + (size_t)h * 128 * HD + j;

    float acc[16];
#pragma unroll
    for (int r = 0; r < 16; r++) acc[r] = 0.f;

    float wbuf[8];
#pragma unroll
    for (int k = 0; k < 8; k++) wbuf[k] = Weh[(size_t)k * HD];

#pragma unroll
    for (int eb = 0; eb < 16; eb++) {
        float wcur[8];
#pragma unroll
        for (int k = 0; k < 8; k++) wcur[k] = wbuf[k];
        if (eb < 15) {
#pragma unroll
            for (int k = 0; k < 8; k++)
                wbuf[k] = Weh[(size_t)((eb + 1) * 8 + k) * HD];
        }
#pragma unroll
        for (int ei = 0; ei < 8; ei++) {
            const int e = eb * 8 + ei;
            const float w = wcur[ei];
            const float* row = &E0t[e * 20];
            float4 r0 = *(const float4*)row;
            float4 r1 = *(const float4*)(row + 4);
            float4 r2 = *(const float4*)(row + 8);
            float4 r3 = *(const float4*)(row + 12);
            acc[0] += r0.x * w;  acc[1] += r0.y * w;
            acc[2] += r0.z * w;  acc[3] += r0.w * w;
            acc[4] += r1.x * w;  acc[5] += r1.y * w;
            acc[6] += r1.z * w;  acc[7] += r1.w * w;
            acc[8] += r2.x * w;  acc[9] += r2.y * w;
            acc[10] += r2.z * w; acc[11] += r2.w * w;
            acc[12] += r3.x * w; acc[13] += r3.y * w;
            acc[14] += r3.z * w; acc[15] += r3.w * w;
        }
    }

#pragma unroll
    for (int r = 0; r < 16; r++)
        g_E1h[((size_t)h * MM + m0 + r) * HD + j] = __float2half_rn(acc[r]);

    const float av = a[h * HD + j];
    float p[16];
#pragma unroll
    for (int r = 0; r < 16; r++) p[r] = acc[r] * av;
#pragma unroll
    for (int o = 16; o; o >>= 1)
#pragma unroll
        for (int r = 0; r < 16; r++) p[r] += __shfl_xor_sync(0xffffffffu, p[r], o);
    const int lane = tid & 31, warp = tid >> 5;
    if (lane == 0)
#pragma unroll
        for (int r = 0; r < 16; r++) dpart[warp][r] = p[r];
    __syncthreads();
    if (tid < 64) {
        int h2 = tid >> 4, r = tid & 15;
        g_d[h2 * MM + m0 + r] = (dpart[2 * h2][r] + dpart[2 * h2 + 1][r]) * LOG2E;
    }
}

// ============================ flash kernel ============================
// block = 128 n-rows x 1 head, 8 warps. 128-m stages, double-buffered.
// W generated in-register (f16x2); B via ldmatrix.x4; Z on the ALU pipe.
__global__ __launch_bounds__(256, 2) void k_flash() {
    __shared__ __align__(16) __half Et[2][128 * 72];   // 144B row stride, 36.9KB
    __shared__ uint32_t dsh[2][64];                    // f16x2 d-pairs (128 m)

    const int t = threadIdx.x, lane = t & 31, wid = t >> 5;
    const int g = lane >> 2, tg = lane & 3;
    const int h = blockIdx.y;
    const int n0 = blockIdx.x * 128;
    const int rowa = n0 + wid * 16 + g, rowb = rowa + 8;
    const float saf = g_s[h * NN + rowa];
    const float sbf = g_s[h * NN + rowb];
    __half2 sa2h = __floats2half2_rn(saf, saf);
    __half2 sb2h = __floats2half2_rn(sbf, sbf);
    const uint32_t sa2 = *(uint32_t*)&sa2h, sb2 = *(uint32_t*)&sb2h;

    float acc[8][4];
#pragma unroll
    for (int i = 0; i < 8; i++)
#pragma unroll
        for (int q = 0; q < 4; q++) acc[i][q] = 0.f;
    float z_a = 0.f, z_b = 0.f;

    const __half* E1p = g_E1h + (size_t)h * MM * HD;
    const float* dh = g_d + h * MM;
    const uint32_t et0 = smem_u32(&Et[0][0]);
    const int lr16 = lane & 15, ct = lane >> 4;        // ldmatrix.x4 mapping

    uint32_t wa[4], wb[4];

    // preload stage 0
#pragma unroll
    for (int k = 0; k < 4; k++) {
        int idx = t + k * 256;
        int row = idx >> 3, c8 = idx & 7;
        *(uint4*)((char*)&Et[0][0] + row * 144 + c8 * 16) =
            *(const uint4*)(E1p + (size_t)row * HD + c8 * 8);
    }
    if (t < 32) {
        float4 dv = *(const float4*)(dh + t * 4);
        __half2 q0 = __floats2half2_rn(dv.x, dv.y);
        __half2 q1 = __floats2half2_rn(dv.z, dv.w);
        dsh[0][2 * t] = *(uint32_t*)&q0;
        dsh[0][2 * t + 1] = *(uint32_t*)&q1;
    }
#pragma unroll
    for (int w = 0; w < 4; w++) {
        wa[w] = g_AbT[(size_t)w * NN + rowa];
        wb[w] = g_AbT[(size_t)w * NN + rowb];
    }
    __syncthreads();

    for (int st = 0; st < MM / 128; st++) {
        const int b = st & 1;
        const bool nxt = (st + 1 < MM / 128);
        uint4 pf[4]; float4 pd;
        uint32_t na[4], nb[4];
        if (nxt) {
            const __half* src = E1p + (size_t)(st + 1) * 128 * HD;
#pragma unroll
            for (int k = 0; k < 4; k++) {
                int idx = t + k * 256;
                pf[k] = *(const uint4*)(src + (size_t)(idx >> 3) * HD + (idx & 7) * 8);
            }
            if (t < 32) pd = *(const float4*)(dh + (st + 1) * 128 + t * 4);
            const size_t wbase = (size_t)(st + 1) * 4 * NN;
#pragma unroll
            for (int w = 0; w < 4; w++) {
                na[w] = g_AbT[wbase + (size_t)w * NN + rowa];
                nb[w] = g_AbT[wbase + (size_t)w * NN + rowb];
            }
        }

        const uint32_t etb = et0 + b * 18432;
        uint32_t zaa = 0u, zab = 0u;        // per-stage f16x2 Z partials

#pragma unroll
        for (int mc = 0; mc < 8; mc++) {
            const uint32_t dp0 = dsh[b][mc * 8 + tg];
            const uint32_t dp1 = dsh[b][mc * 8 + tg + 4];
            const int sh = ((mc & 1) << 4) + 2 * tg;
            const uint32_t ua = wa[mc >> 1] >> sh;
            const uint32_t ub = wb[mc >> 1] >> sh;

            uint32_t a0 = wgen(hadd2u(sa2, dp0)) & mk2(ua);
            uint32_t a1 = wgen(hadd2u(sb2, dp0)) & mk2(ub);
            uint32_t a2 = wgen(hadd2u(sa2, dp1)) & mk2(ua >> 8);
            uint32_t a3 = wgen(hadd2u(sb2, dp1)) & mk2(ub >> 8);

            zaa = hadd2u(zaa, hadd2u(a0, a2));        // Z on ALU pipe
            zab = hadd2u(zab, hadd2u(a1, a3));

            const uint32_t rb = etb + (mc * 16 + lr16) * 144 + ct * 16;
#pragma unroll
            for (int jj = 0; jj < 4; jj++) {
                uint32_t f0, f1, f2, f3;
                asm volatile("ldmatrix.sync.aligned.m8n8.x4.trans.shared.b16 "
                             "{%0,%1,%2,%3}, [%4];"
                             : "=r"(f0), "=r"(f1), "=r"(f2), "=r"(f3)
                             : "r"(rb + jj * 32));
                MMA16816(acc[2 * jj],     a0, a1, a2, a3, f0, f1);
                MMA16816(acc[2 * jj + 1], a0, a1, a2, a3, f2, f3);
            }
        }

        {   // flush stage Z partials to fp32
            float2 va = __half22float2(*(__half2*)&zaa);
            float2 vb = __half22float2(*(__half2*)&zab);
            z_a += va.x + va.y;
            z_b += vb.x + vb.y;
        }

        if (nxt) {
            char* dst = (char*)&Et[b ^ 1][0];
#pragma unroll
            for (int k = 0; k < 4; k++) {
                int idx = t + k * 256;
                *(uint4*)(dst + (idx >> 3) * 144 + (idx & 7) * 16) = pf[k];
            }
            if (t < 32) {
                __half2 q0 = __floats2half2_rn(pd.x, pd.y);
                __half2 q1 = __floats2half2_rn(pd.z, pd.w);
                dsh[b ^ 1][2 * t] = *(uint32_t*)&q0;
                dsh[b ^ 1][2 * t + 1] = *(uint32_t*)&q1;
            }
#pragma unroll
            for (int w = 0; w < 4; w++) { wa[w] = na[w]; wb[w] = nb[w]; }
        }
        __syncthreads();
    }

    // reduce Z across the 4 tg threads sharing each row
    z_a += __shfl_xor_sync(0xffffffffu, z_a, 1);
    z_a += __shfl_xor_sync(0xffffffffu, z_a, 2);
    z_b += __shfl_xor_sync(0xffffffffu, z_b, 1);
    z_b += __shfl_xor_sync(0xffffffffu, z_b, 2);

    // epilogue: per-head partials (race-free, each (h,n) owned by one block)
    float* npa = &g_np[h][rowa][0];
    float* npb = &g_np[h][rowb][0];
#pragma unroll
    for (int j = 0; j < 8; j++) {
        *(float2*)(npa + j * 8 + 2 * tg) = make_float2(acc[j][0], acc[j][1]);
        *(float2*)(npb + j * 8 + 2 * tg) = make_float2(acc[j][2], acc[j][3]);
    }
    if (tg == 0) { g_zp[h][rowa] = z_a; g_zp[h][rowb] = z_b; }
}

// combine heads: mean(num/Z) then softmax over 64 -> out
__global__ void k_comb(float* __restrict__ out) {
    int warp = threadIdx.x >> 5, lane = threadIdx.x & 31;
    int n = blockIdx.x * 8 + warp;
    float v0 = 0.f, v1 = 0.f;
#pragma unroll
    for (int h = 0; h < NH; h++) {
        float inv = 1.0f / g_zp[h][n];
        v0 += g_np[h][n][lane] * inv;
        v1 += g_np[h][n][lane + 32] * inv;
    }
    v0 *= 0.25f; v1 *= 0.25f;
    float mx = fmaxf(v0, v1);
#pragma unroll
    for (int o = 16; o; o >>= 1) mx = fmaxf(mx, __shfl_xor_sync(0xffffffffu, mx, o));
    float e0 = __expf(v0 - mx), e1 = __expf(v1 - mx);
    float s = e0 + e1;
#pragma unroll
    for (int o = 16; o; o >>= 1) s += __shfl_xor_sync(0xffffffffu, s, o);
    float r = 1.0f / s;
    out[(size_t)n * HD + lane] = e0 * r;
    out[(size_t)n * HD + 32 + lane] = e1 * r;
}

// ============================ launch ============================
extern "C" void kernel_launch(void* const* d_in, const int* in_sizes, int n_in,
                              void* d_out, int out_size) {
    const float* F0 = (const float*)d_in[0];
    const float* E0 = (const float*)d_in[1];
    const int*   A  = (const int*)d_in[2];
    const float* Wf = (const float*)d_in[3];
    const float* We = (const float*)d_in[4];
    const float* a  = (const float*)d_in[5];
    float* out = (float*)d_out;
    (void)in_sizes; (void)n_in; (void)out_size;

    k_pack<<<2048, 256>>>(A);
    k_wfa<<<64, 256>>>(Wf, a);
    k_s<<<4096, 256>>>(F0);
    k_e1<<<MM / 16, 256>>>(E0, We, a);
    k_flash<<<dim3(NN / 128, NH), 256>>>();
    k_comb<<<NN / 8, 256>>>(out);
}

// round 15
// speedup vs baseline: 1.0925x; 1.0925x over previous
#include <cuda_runtime.h>
#include <cuda_fp16.h>
#include <cstdint>

#define NN 8192
#define MM 8192
#define HD 64
#define NH 4
#define LOG2E 1.4426950408889634f

// ---- scratch (device globals; no allocations allowed) ----
__device__ float g_s[NH * NN];                              // pre-scaled by log2e
__device__ float g_d[NH * MM];                              // pre-scaled by log2e
__device__ float g_wfa[NH * 128];
__device__ __align__(16) __half g_E1h[(size_t)NH * MM * HD]; // [h][m][j] 4MB
__device__ uint32_t g_AbT[(size_t)(MM / 32) * NN];          // [m/32][n] 8MB
__device__ float g_np[NH][NN][HD];                          // per-head numerators 8MB
__device__ float g_zp[NH][NN];                              // per-head Z

__device__ __forceinline__ uint32_t smem_u32(const void* p) {
    uint32_t a;
    asm("{ .reg .u64 t; cvta.to.shared.u64 t, %1; cvt.u32.u64 %0, t; }" : "=r"(a) : "l"(p));
    return a;
}
__device__ __forceinline__ uint32_t hadd2u(uint32_t a, uint32_t b) {
    uint32_t r; asm("add.f16x2 %0,%1,%2;" : "=r"(r) : "r"(a), "r"(b)); return r;
}
__device__ __forceinline__ uint32_t hmul2u(uint32_t a, uint32_t b) {
    uint32_t r; asm("mul.f16x2 %0,%1,%2;" : "=r"(r) : "r"(a), "r"(b)); return r;
}
__device__ __forceinline__ uint32_t hmax2u(uint32_t a, uint32_t b) {
    uint32_t r; asm("max.f16x2 %0,%1,%2;" : "=r"(r) : "r"(a), "r"(b)); return r;
}
__device__ __forceinline__ uint32_t ex2h2(uint32_t a) {
    uint32_t r; asm("ex2.approx.f16x2 %0,%1;" : "=r"(r) : "r"(a)); return r;
}
// leaky_relu then exp2 on packed f16x2
__device__ __forceinline__ uint32_t wgen(uint32_t x) {
    return ex2h2(hmax2u(x, hmul2u(x, 0x32663266u)));   // 0x3266 = 0.2f16
}
// mask from 2 bits (bit0 -> low half, bit1 -> high half)
__device__ __forceinline__ uint32_t mk2(uint32_t u) {
    return (u & 1u) * 0xFFFFu + (u & 2u) * 0x7FFF8000u;
}
#define MMA16816(acc, a0, a1, a2, a3, b0, b1)                                  \
    asm volatile("mma.sync.aligned.m16n8k16.row.col.f32.f16.f16.f32 "          \
                 "{%0,%1,%2,%3}, {%4,%5,%6,%7}, {%8,%9}, {%0,%1,%2,%3};"       \
                 : "+f"(acc[0]), "+f"(acc[1]), "+f"(acc[2]), "+f"(acc[3])      \
                 : "r"(a0), "r"(a1), "r"(a2), "r"(a3), "r"(b0), "r"(b1))

// ============================ stage kernels ============================
// wfa: one warp per (h,f) output. 64 blocks x 256 threads = 512 warps.
__global__ void k_wfa(const float* __restrict__ Wf, const float* __restrict__ a) {
    int gw = (blockIdx.x * blockDim.x + threadIdx.x) >> 5;
    int lane = threadIdx.x & 31;
    int h = gw >> 7, f = gw & 127;
    const float* wp = Wf + ((size_t)h * 128 + f) * HD;
    const float* ap = a + h * HD;
    float s = wp[lane] * ap[lane] + wp[lane + 32] * ap[lane + 32];
#pragma unroll
    for (int o = 16; o; o >>= 1) s += __shfl_xor_sync(0xffffffffu, s, o);
    if (lane == 0) g_wfa[gw] = s;
}

// Pack A -> transposed bitmask. 4 independent rows per warp-iteration (MLP=4).
__global__ void k_pack(const int* __restrict__ A) {
    int lane = threadIdx.x & 31;
    int gw = (blockIdx.x * blockDim.x + threadIdx.x) >> 5;
    int nw = (gridDim.x * blockDim.x) >> 5;
    for (int idx = gw; idx < (MM / 32) * (NN / 4); idx += nw) {
        int w = idx & 255;           // MM/32 = 256
        int n4 = idx >> 8;
        const int* base = A + (size_t)(n4 * 4) * MM + w * 32 + lane;
        int v0 = base[0];
        int v1 = base[MM];
        int v2 = base[2 * MM];
        int v3 = base[3 * MM];
        uint32_t b0 = __ballot_sync(0xffffffffu, v0 > 0);
        uint32_t b1 = __ballot_sync(0xffffffffu, v1 > 0);
        uint32_t b2 = __ballot_sync(0xffffffffu, v2 > 0);
        uint32_t b3 = __ballot_sync(0xffffffffu, v3 > 0);
        if (lane == 0) {
            uint32_t* dst = g_AbT + (size_t)w * NN + n4 * 4;
            dst[0] = b0; dst[1] = b1; dst[2] = b2; dst[3] = b3;
        }
    }
}

// s[h,n] = (F0[n,:] . wfa[h,:]) * log2e
__global__ void k_s(const float* __restrict__ F0) {
    int warp = threadIdx.x >> 5, lane = threadIdx.x & 31;
    int gw = blockIdx.x * 8 + warp;
    int n = gw & (NN - 1), h = gw >> 13;
    const float* fp = F0 + (size_t)n * 128;
    const float* wp = g_wfa + h * 128;
    float s = 0.f;
#pragma unroll
    for (int k = 0; k < 4; k++) { int f = lane + k * 32; s += fp[f] * wp[f]; }
#pragma unroll
    for (int o = 16; o; o >>= 1) s += __shfl_xor_sync(0xffffffffu, s, o);
    if (lane == 0) g_s[h * NN + n] = s * LOG2E;
}

// ============================ e1 on tensor cores ============================
// Block = 128 m-rows x 1 head. E0 tile + We converted to f16 in smem, then
// D[128x64] = E0f16 @ Wef16 via mma.sync (fp32 accum). E1 stored f16; d
// computed from the fp32 accumulator fragments (dot with a + tg-shuffle).
#define E0S_STRIDE 272          // 128 f16 cols * 2B + 16B pad
#define WES_STRIDE 144          // 64 f16 cols * 2B + 16B pad
#define E1_SMEM (128 * E0S_STRIDE + 128 * WES_STRIDE + 256)   // 53504 B

__global__ __launch_bounds__(256) void k_e1mma(const float* __restrict__ E0,
                                               const float* __restrict__ We,
                                               const float* __restrict__ a) {
    extern __shared__ char sm[];
    char* E0s = sm;                              // [128][E0S_STRIDE]
    char* Wes = sm + 128 * E0S_STRIDE;           // [128][WES_STRIDE]
    float* ash = (float*)(sm + 128 * E0S_STRIDE + 128 * WES_STRIDE);

    const int t = threadIdx.x, lane = t & 31, wid = t >> 5;
    const int g = lane >> 2, tg = lane & 3;
    const int m0 = blockIdx.x * 128;
    const int h = blockIdx.y;

    // stage E0 tile -> f16 (4096 float4 groups, 16 per thread)
#pragma unroll
    for (int k = 0; k < 16; k++) {
        int idx = t + k * 256;
        int row = idx >> 5, c4 = idx & 31;
        float4 v = *(const float4*)(E0 + (size_t)(m0 + row) * 128 + c4 * 4);
        __half2 p0 = __floats2half2_rn(v.x, v.y);
        __half2 p1 = __floats2half2_rn(v.z, v.w);
        *(uint2*)(E0s + row * E0S_STRIDE + c4 * 8) =
            make_uint2(*(uint32_t*)&p0, *(uint32_t*)&p1);
    }
    // stage We[h] -> f16 (2048 float4 groups, 8 per thread)
#pragma unroll
    for (int k = 0; k < 8; k++) {
        int idx = t + k * 256;
        int row = idx >> 4, c4 = idx & 15;
        float4 v = *(const float4*)(We + ((size_t)h * 128 + row) * HD + c4 * 4);
        __half2 p0 = __floats2half2_rn(v.x, v.y);
        __half2 p1 = __floats2half2_rn(v.z, v.w);
        *(uint2*)(Wes + row * WES_STRIDE + c4 * 8) =
            make_uint2(*(uint32_t*)&p0, *(uint32_t*)&p1);
    }
    if (t < 64) ash[t] = a[h * HD + t];
    __syncthreads();

    float acc[8][4];
#pragma unroll
    for (int i = 0; i < 8; i++)
#pragma unroll
        for (int q = 0; q < 4; q++) acc[i][q] = 0.f;

    const uint32_t e0b = smem_u32(E0s);
    const uint32_t web = smem_u32(Wes);
    const int lr16 = lane & 15, ct = lane >> 4;
    // A-operand lane address: row = wid*16 + (lane&15), col16 = (lane>>4)
    const uint32_t aaddr0 = e0b + (wid * 16 + lr16) * E0S_STRIDE + ct * 16;

#pragma unroll
    for (int kt = 0; kt < 8; kt++) {
        uint32_t a0, a1, a2, a3;
        asm volatile("ldmatrix.sync.aligned.m8n8.x4.shared.b16 {%0,%1,%2,%3}, [%4];"
                     : "=r"(a0), "=r"(a1), "=r"(a2), "=r"(a3)
                     : "r"(aaddr0 + kt * 32));
        const uint32_t rb = web + (kt * 16 + lr16) * WES_STRIDE + ct * 16;
#pragma unroll
        for (int jj = 0; jj < 4; jj++) {
            uint32_t f0, f1, f2, f3;
            asm volatile("ldmatrix.sync.aligned.m8n8.x4.trans.shared.b16 "
                         "{%0,%1,%2,%3}, [%4];"
                         : "=r"(f0), "=r"(f1), "=r"(f2), "=r"(f3)
                         : "r"(rb + jj * 32));
            MMA16816(acc[2 * jj],     a0, a1, a2, a3, f0, f1);
            MMA16816(acc[2 * jj + 1], a0, a1, a2, a3, f2, f3);
        }
    }

    // store E1 (f16) and compute d from fragments
    const int rowa = m0 + wid * 16 + g, rowb = rowa + 8;
    float pa = 0.f, pb = 0.f;
#pragma unroll
    for (int jt = 0; jt < 8; jt++) {
        __half2 q0 = __floats2half2_rn(acc[jt][0], acc[jt][1]);
        __half2 q1 = __floats2half2_rn(acc[jt][2], acc[jt][3]);
        *(uint32_t*)&g_E1h[((size_t)h * MM + rowa) * HD + jt * 8 + 2 * tg] = *(uint32_t*)&q0;
        *(uint32_t*)&g_E1h[((size_t)h * MM + rowb) * HD + jt * 8 + 2 * tg] = *(uint32_t*)&q1;
        float av0 = ash[jt * 8 + 2 * tg], av1 = ash[jt * 8 + 2 * tg + 1];
        pa += acc[jt][0] * av0 + acc[jt][1] * av1;
        pb += acc[jt][2] * av0 + acc[jt][3] * av1;
    }
    pa += __shfl_xor_sync(0xffffffffu, pa, 1);
    pa += __shfl_xor_sync(0xffffffffu, pa, 2);
    pb += __shfl_xor_sync(0xffffffffu, pb, 1);
    pb += __shfl_xor_sync(0xffffffffu, pb, 2);
    if (tg == 0) {
        g_d[h * MM + rowa] = pa * LOG2E;
        g_d[h * MM + rowb] = pb * LOG2E;
    }
}

// ============================ flash kernel ============================
// block = 128 n-rows x 1 head, 8 warps. 128-m stages, double-buffered.
// W generated in-register (f16x2); B via ldmatrix.x4; Z on the ALU pipe.
__global__ __launch_bounds__(256, 2) void k_flash() {
    __shared__ __align__(16) __half Et[2][128 * 72];   // 144B row stride, 36.9KB
    __shared__ uint32_t dsh[2][64];                    // f16x2 d-pairs (128 m)

    const int t = threadIdx.x, lane = t & 31, wid = t >> 5;
    const int g = lane >> 2, tg = lane & 3;
    const int h = blockIdx.y;
    const int n0 = blockIdx.x * 128;
    const int rowa = n0 + wid * 16 + g, rowb = rowa + 8;
    const float saf = g_s[h * NN + rowa];
    const float sbf = g_s[h * NN + rowb];
    __half2 sa2h = __floats2half2_rn(saf, saf);
    __half2 sb2h = __floats2half2_rn(sbf, sbf);
    const uint32_t sa2 = *(uint32_t*)&sa2h, sb2 = *(uint32_t*)&sb2h;

    float acc[8][4];
#pragma unroll
    for (int i = 0; i < 8; i++)
#pragma unroll
        for (int q = 0; q < 4; q++) acc[i][q] = 0.f;
    float z_a = 0.f, z_b = 0.f;

    const __half* E1p = g_E1h + (size_t)h * MM * HD;
    const float* dh = g_d + h * MM;
    const uint32_t et0 = smem_u32(&Et[0][0]);
    const int lr16 = lane & 15, ct = lane >> 4;        // ldmatrix.x4 mapping

    uint32_t wa[4], wb[4];

    // preload stage 0
#pragma unroll
    for (int k = 0; k < 4; k++) {
        int idx = t + k * 256;
        int row = idx >> 3, c8 = idx & 7;
        *(uint4*)((char*)&Et[0][0] + row * 144 + c8 * 16) =
            *(const uint4*)(E1p + (size_t)row * HD + c8 * 8);
    }
    if (t < 32) {
        float4 dv = *(const float4*)(dh + t * 4);
        __half2 q0 = __floats2half2_rn(dv.x, dv.y);
        __half2 q1 = __floats2half2_rn(dv.z, dv.w);
        dsh[0][2 * t] = *(uint32_t*)&q0;
        dsh[0][2 * t + 1] = *(uint32_t*)&q1;
    }
#pragma unroll
    for (int w = 0; w < 4; w++) {
        wa[w] = g_AbT[(size_t)w * NN + rowa];
        wb[w] = g_AbT[(size_t)w * NN + rowb];
    }
    __syncthreads();

    for (int st = 0; st < MM / 128; st++) {
        const int b = st & 1;
        const bool nxt = (st + 1 < MM / 128);
        uint4 pf[4]; float4 pd;
        uint32_t na[4], nb[4];
        if (nxt) {
            const __half* src = E1p + (size_t)(st + 1) * 128 * HD;
#pragma unroll
            for (int k = 0; k < 4; k++) {
                int idx = t + k * 256;
                pf[k] = *(const uint4*)(src + (size_t)(idx >> 3) * HD + (idx & 7) * 8);
            }
            if (t < 32) pd = *(const float4*)(dh + (st + 1) * 128 + t * 4);
            const size_t wbase = (size_t)(st + 1) * 4 * NN;
#pragma unroll
            for (int w = 0; w < 4; w++) {
                na[w] = g_AbT[wbase + (size_t)w * NN + rowa];
                nb[w] = g_AbT[wbase + (size_t)w * NN + rowb];
            }
        }

        const uint32_t etb = et0 + b * 18432;
        uint32_t zaa = 0u, zab = 0u;        // per-stage f16x2 Z partials

#pragma unroll
        for (int mc = 0; mc < 8; mc++) {
            const uint32_t dp0 = dsh[b][mc * 8 + tg];
            const uint32_t dp1 = dsh[b][mc * 8 + tg + 4];
            const int sh = ((mc & 1) << 4) + 2 * tg;
            const uint32_t ua = wa[mc >> 1] >> sh;
            const uint32_t ub = wb[mc >> 1] >> sh;

            uint32_t a0 = wgen(hadd2u(sa2, dp0)) & mk2(ua);
            uint32_t a1 = wgen(hadd2u(sb2, dp0)) & mk2(ub);
            uint32_t a2 = wgen(hadd2u(sa2, dp1)) & mk2(ua >> 8);
            uint32_t a3 = wgen(hadd2u(sb2, dp1)) & mk2(ub >> 8);

            zaa = hadd2u(zaa, hadd2u(a0, a2));        // Z on ALU pipe
            zab = hadd2u(zab, hadd2u(a1, a3));

            const uint32_t rb = etb + (mc * 16 + lr16) * 144 + ct * 16;
#pragma unroll
            for (int jj = 0; jj < 4; jj++) {
                uint32_t f0, f1, f2, f3;
                asm volatile("ldmatrix.sync.aligned.m8n8.x4.trans.shared.b16 "
                             "{%0,%1,%2,%3}, [%4];"
                             : "=r"(f0), "=r"(f1), "=r"(f2), "=r"(f3)
                             : "r"(rb + jj * 32));
                MMA16816(acc[2 * jj],     a0, a1, a2, a3, f0, f1);
                MMA16816(acc[2 * jj + 1], a0, a1, a2, a3, f2, f3);
            }
        }

        {   // flush stage Z partials to fp32
            float2 va = __half22float2(*(__half2*)&zaa);
            float2 vb = __half22float2(*(__half2*)&zab);
            z_a += va.x + va.y;
            z_b += vb.x + vb.y;
        }

        if (nxt) {
            char* dst = (char*)&Et[b ^ 1][0];
#pragma unroll
            for (int k = 0; k < 4; k++) {
                int idx = t + k * 256;
                *(uint4*)(dst + (idx >> 3) * 144 + (idx & 7) * 16) = pf[k];
            }
            if (t < 32) {
                __half2 q0 = __floats2half2_rn(pd.x, pd.y);
                __half2 q1 = __floats2half2_rn(pd.z, pd.w);
                dsh[b ^ 1][2 * t] = *(uint32_t*)&q0;
                dsh[b ^ 1][2 * t + 1] = *(uint32_t*)&q1;
            }
#pragma unroll
            for (int w = 0; w < 4; w++) { wa[w] = na[w]; wb[w] = nb[w]; }
        }
        __syncthreads();
    }

    // reduce Z across the 4 tg threads sharing each row
    z_a += __shfl_xor_sync(0xffffffffu, z_a, 1);
    z_a += __shfl_xor_sync(0xffffffffu, z_a, 2);
    z_b += __shfl_xor_sync(0xffffffffu, z_b, 1);
    z_b += __shfl_xor_sync(0xffffffffu, z_b, 2);

    // epilogue: per-head partials (race-free, each (h,n) owned by one block)
    float* npa = &g_np[h][rowa][0];
    float* npb = &g_np[h][rowb][0];
#pragma unroll
    for (int j = 0; j < 8; j++) {
        *(float2*)(npa + j * 8 + 2 * tg) = make_float2(acc[j][0], acc[j][1]);
        *(float2*)(npb + j * 8 + 2 * tg) = make_float2(acc[j][2], acc[j][3]);
    }
    if (tg == 0) { g_zp[h][rowa] = z_a; g_zp[h][rowb] = z_b; }
}

// combine heads: mean(num/Z) then softmax over 64 -> out
__global__ void k_comb(float* __restrict__ out) {
    int warp = threadIdx.x >> 5, lane = threadIdx.x & 31;
    int n = blockIdx.x * 8 + warp;
    float v0 = 0.f, v1 = 0.f;
#pragma unroll
    for (int h = 0; h < NH; h++) {
        float inv = 1.0f / g_zp[h][n];
        v0 += g_np[h][n][lane] * inv;
        v1 += g_np[h][n][lane + 32] * inv;
    }
    v0 *= 0.25f; v1 *= 0.25f;
    float mx = fmaxf(v0, v1);
#pragma unroll
    for (int o = 16; o; o >>= 1) mx = fmaxf(mx, __shfl_xor_sync(0xffffffffu, mx, o));
    float e0 = __expf(v0 - mx), e1 = __expf(v1 - mx);
    float s = e0 + e1;
#pragma unroll
    for (int o = 16; o; o >>= 1) s += __shfl_xor_sync(0xffffffffu, s, o);
    float r = 1.0f / s;
    out[(size_t)n * HD + lane] = e0 * r;
    out[(size_t)n * HD + 32 + lane] = e1 * r;
}

// ============================ launch ============================
extern "C" void kernel_launch(void* const* d_in, const int* in_sizes, int n_in,
                              void* d_out, int out_size) {
    const float* F0 = (const float*)d_in[0];
    const float* E0 = (const float*)d_in[1];
    const int*   A  = (const int*)d_in[2];
    const float* Wf = (const float*)d_in[3];
    const float* We = (const float*)d_in[4];
    const float* a  = (const float*)d_in[5];
    float* out = (float*)d_out;
    (void)in_sizes; (void)n_in; (void)out_size;

    static int init_done = 0;
    if (!init_done) {
        cudaFuncSetAttribute(k_e1mma, cudaFuncAttributeMaxDynamicSharedMemorySize, E1_SMEM);
        init_done = 1;
    }

    cudaStream_t s2 = 0;
    cudaEvent_t evFork = 0, evJoin = 0;
    bool forked = false;
    if (cudaStreamCreateWithFlags(&s2, cudaStreamNonBlocking) == cudaSuccess &&
        cudaEventCreateWithFlags(&evFork, cudaEventDisableTiming) == cudaSuccess &&
        cudaEventCreateWithFlags(&evJoin, cudaEventDisableTiming) == cudaSuccess) {
        forked = (cudaEventRecord(evFork, 0) == cudaSuccess) &&
                 (cudaStreamWaitEvent(s2, evFork, 0) == cudaSuccess);
    }

    if (forked) {
        k_pack<<<2048, 256, 0, s2>>>(A);
        cudaEventRecord(evJoin, s2);
    } else {
        k_pack<<<2048, 256>>>(A);
    }

    k_wfa<<<64, 256>>>(Wf, a);
    k_s<<<4096, 256>>>(F0);
    k_e1mma<<<dim3(MM / 128, NH), 256, E1_SMEM>>>(E0, We, a);

    if (forked) cudaStreamWaitEvent(0, evJoin, 0);

    k_flash<<<dim3(NN / 128, NH), 256>>>();
    k_comb<<<NN / 8, 256>>>(out);

    if (evFork) cudaEventDestroy(evFork);
    if (evJoin) cudaEventDestroy(evJoin);
    if (s2) cudaStreamDestroy(s2);
}